// round 13
// baseline (speedup 1.0000x reference)
#include <cuda_runtime.h>
#include <cuda_fp16.h>
#include <math.h>

// ---------------- problem constants ----------------
#define BB 64
#define NN 431
#define CC 256
#define HH 56
#define WW 56
#define HW (HH*WW)            // 3136
#define NPTS (BB*NN)          // 27584
#define TILE_P 96
#define NTILES ((NPTS + TILE_P - 1) / TILE_P)   // 288 -> one wave at 2 blocks/SM
#define THREADS 512

// ---------------- smem map (byte offsets) ----------------
#define SM_FEAT 0                        // feat [96 r][256 k] fp16, stride 512B, swz (48KB)
#define SM_Y0   49152                    // y0 [96][128] fp16, stride 256B (24KB)
#define SM_Y1   SM_Y0                    // y1 [96][64] fp16, stride 128B (12KB), aliases y0
#define SM_BUF  73728                    // 2 x 16KB weight double-buffer
#define SM_W2   106496                   // W2 [8][320] fp16, stride 640B (5KB = 320 x 16B lines)
#define SM_TOTAL 111616                  // -> 2 blocks/SM (223KB/SM)

// ---------------- global scratch ----------------
// W0: 4 chunks of [128 o][64 k] (stride 128B, swz), 16KB each
// W1: 3 chunks of [64 o][128 k] (stride 256B, swz), 16KB each
__device__ __align__(16) unsigned char g_W0s[4*16384];
__device__ __align__(16) unsigned char g_W1s[3*16384];
__device__ __align__(16) unsigned char g_W2s[8*320*2];     // rows 5..7 zero
__device__ __half g_sfT[(size_t)BB * HW * CC];             // (B, HW, C) fp16

// ---------------- helpers ----------------
__device__ __forceinline__ int tile_off(int r, int k, int S) {
    int c16 = k >> 3;
    return r * S + ((((c16 & ~7) | ((c16 ^ r) & 7))) << 4) + ((k & 7) << 1);
}
__device__ __forceinline__ unsigned smem_u32(const void* p) {
    unsigned a;
    asm("{ .reg .u64 t; cvta.to.shared.u64 t, %1; cvt.u32.u64 %0, t; }" : "=r"(a) : "l"(p));
    return a;
}
__device__ __forceinline__ void cp_async16(unsigned sdst, const void* gsrc) {
    asm volatile("cp.async.cg.shared.global [%0], [%1], 16;" :: "r"(sdst), "l"(gsrc));
}
__device__ __forceinline__ void stage16k(unsigned sdst, const unsigned char* gsrc, int tid) {
    #pragma unroll
    for (int i = 0; i < 2; i++)
        cp_async16(sdst + (tid + i * 512) * 16, gsrc + (tid + i * 512) * 16);
    asm volatile("cp.async.commit_group;");
}
__device__ __forceinline__ void ldm_x4(unsigned r[4], unsigned addr) {
    asm volatile("ldmatrix.sync.aligned.m8n8.x4.shared.b16 {%0,%1,%2,%3}, [%4];"
                 : "=r"(r[0]), "=r"(r[1]), "=r"(r[2]), "=r"(r[3]) : "r"(addr));
}
__device__ __forceinline__ void ldm_x2(unsigned r[2], unsigned addr) {
    asm volatile("ldmatrix.sync.aligned.m8n8.x2.shared.b16 {%0,%1}, [%2];"
                 : "=r"(r[0]), "=r"(r[1]) : "r"(addr));
}
__device__ __forceinline__ void mma_16816(float d[4], const unsigned a[4], unsigned b0, unsigned b1) {
    asm volatile("mma.sync.aligned.m16n8k16.row.col.f32.f16.f16.f32 "
        "{%0,%1,%2,%3}, {%4,%5,%6,%7}, {%8,%9}, {%0,%1,%2,%3};"
        : "+f"(d[0]), "+f"(d[1]), "+f"(d[2]), "+f"(d[3])
        : "r"(a[0]), "r"(a[1]), "r"(a[2]), "r"(a[3]), "r"(b0), "r"(b1));
}
__device__ __forceinline__ float lrelu(float v) { return (v > 0.f) ? v : 0.01f * v; }

// ---------------- transpose + weight prep ----------------
__global__ __launch_bounds__(256)
void transpose_kernel(const float* __restrict__ sf,
                      const float* __restrict__ W0,
                      const float* __restrict__ W1,
                      const float* __restrict__ W2) {
    __shared__ float tile[32][33];
    const int b  = blockIdx.z;
    const int c0 = blockIdx.y * 32;
    const int p0 = blockIdx.x * 32;
    const int tx = threadIdx.x, ty = threadIdx.y;
    const int t  = ty * 32 + tx;

    {   // weight prep over first 234 flat blocks (59904 = 234*256)
        int fb = (blockIdx.z * 8 + blockIdx.y) * 98 + blockIdx.x;
        if (fb < 234) {
            int i = fb * 256 + t;
            if (i < 32768) {
                int o = i >> 8, k = i & 255;
                *(__half*)(g_W0s + (k >> 6) * 16384 + tile_off(o, k & 63, 128)) =
                    __float2half(W0[o * 256 + k]);
            } else if (i < 32768 + 24576) {
                int j = i - 32768, o = j / 384, k = j - o * 384;
                *(__half*)(g_W1s + (k >> 7) * 16384 + tile_off(o, k & 127, 256)) =
                    __float2half(W1[o * 384 + k]);
            } else {
                int j = i - 32768 - 24576, o = j / 320, k = j - o * 320;
                float v = (o < 5) ? W2[o * 320 + k] : 0.f;
                *(__half*)(g_W2s + tile_off(o, k, 640)) = __float2half(v);
            }
        }
    }

    const float* src = sf + (size_t)b * CC * HW;
    #pragma unroll
    for (int j = 0; j < 4; j++)
        tile[ty * 4 + j][tx] = src[(size_t)(c0 + ty * 4 + j) * HW + p0 + tx];
    __syncthreads();
    const int pr  = t >> 3;
    const int ch4 = t & 7;
    __half2 v0 = __floats2half2_rn(tile[4 * ch4 + 0][pr], tile[4 * ch4 + 1][pr]);
    __half2 v1 = __floats2half2_rn(tile[4 * ch4 + 2][pr], tile[4 * ch4 + 3][pr]);
    uint2 pkt = make_uint2(*(unsigned*)&v0, *(unsigned*)&v1);
    uint2* dst = (uint2*)(g_sfT + (size_t)b * HW * CC + (size_t)(p0 + pr) * CC + c0);
    dst[ch4] = pkt;
}

// ---------------- fused: gather + 3-layer MLP, 96-pt tiles, 512 thr, 2 blocks/SM ----------------
__global__ __launch_bounds__(THREADS, 2)
void maf_fused(const float* __restrict__ p, const float* __restrict__ cam,
               const float* __restrict__ b0, const float* __restrict__ b1,
               const float* __restrict__ b2, float* __restrict__ out)
{
    extern __shared__ char smem[];
    const unsigned sbase = smem_u32(smem);
    const int tid  = threadIdx.x;
    const int warp = tid >> 5;
    const int lane = tid & 31;
    const int tile = blockIdx.x;

    // group 0: W2 (320 x 16B lines) + W0 chunk0
    {
        if (tid < 320)                                    // FIX: was 640 (OOB past SM_TOTAL)
            cp_async16(sbase + SM_W2 + tid * 16, g_W2s + tid * 16);
        #pragma unroll
        for (int i = 0; i < 2; i++)
            cp_async16(sbase + SM_BUF + (tid + i * 512) * 16, g_W0s + (tid + i * 512) * 16);
        asm volatile("cp.async.commit_group;");
    }

    // gather: threads 0..383, pt = tid>>2, channel quarter = tid&3 (64 ch each)
    if (tid < 4 * TILE_P) {
        const int pt = tid >> 2;
        int gp = tile * TILE_P + pt;
        if (gp >= NPTS) gp = NPTS - 1;
        const int b = gp / NN;
        float s  = cam[b * 3 + 0];
        float tx = cam[b * 3 + 1];
        float ty = cam[b * 3 + 2];
        float gx = (s * (p[gp * 3 + 0] + tx) + 1.f) * (0.5f * (WW - 1));
        float gy = (s * (p[gp * 3 + 1] + ty) + 1.f) * (0.5f * (HH - 1));
        float x0f = floorf(gx), y0f = floorf(gy);
        float wx1 = gx - x0f, wy1 = gy - y0f;
        float wx0 = 1.f - wx1, wy0 = 1.f - wy1;
        if (!(x0f       >= 0.f && x0f       <= (float)(WW - 1))) wx0 = 0.f;
        if (!(x0f + 1.f >= 0.f && x0f + 1.f <= (float)(WW - 1))) wx1 = 0.f;
        if (!(y0f       >= 0.f && y0f       <= (float)(HH - 1))) wy0 = 0.f;
        if (!(y0f + 1.f >= 0.f && y0f + 1.f <= (float)(HH - 1))) wy1 = 0.f;
        int ix0 = (int)fminf(fmaxf(x0f,       0.f), (float)(WW - 1));
        int ix1 = (int)fminf(fmaxf(x0f + 1.f, 0.f), (float)(WW - 1));
        int iy0 = (int)fminf(fmaxf(y0f,       0.f), (float)(HH - 1));
        int iy1 = (int)fminf(fmaxf(y0f + 1.f, 0.f), (float)(HH - 1));
        int base = b * HW;
        const int o00 = (base + iy0 * WW + ix0) * CC;
        const int o10 = (base + iy0 * WW + ix1) * CC;
        const int o01 = (base + iy1 * WW + ix0) * CC;
        const int o11 = (base + iy1 * WW + ix1) * CC;
        const float w00 = wx0 * wy0, w10 = wx1 * wy0;
        const float w01 = wx0 * wy1, w11 = wx1 * wy1;

        const int cbase = (tid & 3) * 64;
        #pragma unroll 4
        for (int j = 0; j < 8; j++) {
            const int c = cbase + j * 8;
            uint4 A  = *(const uint4*)(g_sfT + o00 + c);
            uint4 Bv = *(const uint4*)(g_sfT + o10 + c);
            uint4 Cv = *(const uint4*)(g_sfT + o01 + c);
            uint4 Dv = *(const uint4*)(g_sfT + o11 + c);
            __half2 hh[4];
            #pragma unroll
            for (int q = 0; q < 4; q++) {
                float2 fa = __half22float2(((const __half2*)&A)[q]);
                float2 fb = __half22float2(((const __half2*)&Bv)[q]);
                float2 fc = __half22float2(((const __half2*)&Cv)[q]);
                float2 fd = __half22float2(((const __half2*)&Dv)[q]);
                float rx = w00 * fa.x + w10 * fb.x + w01 * fc.x + w11 * fd.x;
                float ry = w00 * fa.y + w10 * fb.y + w01 * fc.y + w11 * fd.y;
                hh[q] = __floats2half2_rn(rx, ry);
            }
            *(uint4*)(smem + SM_FEAT + tile_off(pt, c, 512)) = *(uint4*)hh;
        }
    }

    const int qr = lane >> 2;          // 0..7
    const int qc = (lane & 3) * 2;     // 0,2,4,6
    const int ar = lane & 15, ak = (lane >> 4) * 8;
    const int br = (lane & 7) + ((lane >> 4) << 3), bk = ((lane >> 3) & 1) * 8;

    // ---------------- layer0: D0[96,128], K=256; 16 warps: 48 rows x 16 outs each ----------------
    float d0[3][2][4];
    #pragma unroll
    for (int i = 0; i < 3; i++)
        #pragma unroll
        for (int j = 0; j < 2; j++)
            #pragma unroll
            for (int q = 0; q < 4; q++) d0[i][j][q] = 0.f;
    {
        const int m0 = (warp & 1) * 48;
        const int n0 = (warp >> 1) * 16;
        for (int c = 0; c < 4; c++) {
            if (c < 3)
                stage16k(sbase + SM_BUF + ((c + 1) & 1) * 16384, g_W0s + (c + 1) * 16384, tid);
            else
                stage16k(sbase + SM_BUF + 0 * 16384, g_W1s, tid);
            asm volatile("cp.async.wait_group 1;");
            __syncthreads();          // chunk c (and gather on c==0) visible
            const unsigned bufc = sbase + SM_BUF + (c & 1) * 16384;
            #pragma unroll
            for (int k16 = 0; k16 < 4; k16++) {
                const int kg = c * 64 + k16 * 16;
                const int kl = k16 * 16;
                unsigned a[3][4];
                #pragma unroll
                for (int mt = 0; mt < 3; mt++)
                    ldm_x4(a[mt], sbase + SM_FEAT + tile_off(m0 + mt * 16 + ar, kg + ak, 512));
                unsigned bfr[4];
                ldm_x4(bfr, bufc + tile_off(n0 + br, kl + bk, 128));
                #pragma unroll
                for (int mt = 0; mt < 3; mt++) {
                    mma_16816(d0[mt][0], a[mt], bfr[0], bfr[1]);
                    mma_16816(d0[mt][1], a[mt], bfr[2], bfr[3]);
                }
            }
            __syncthreads();
        }
    }

    // epilogue0: bias + leaky -> y0 (stride 256); overlaps W1 chunk0 cp.async
    {
        const int m0 = (warp & 1) * 48;
        const int n0 = (warp >> 1) * 16;
        #pragma unroll
        for (int mt = 0; mt < 3; mt++)
            #pragma unroll
            for (int nt = 0; nt < 2; nt++) {
                int row = m0 + mt * 16 + qr;
                int o   = n0 + nt * 8 + qc;
                float bx = __ldg(b0 + o), by = __ldg(b0 + o + 1);
                __half2 h0 = __floats2half2_rn(lrelu(d0[mt][nt][0] + bx), lrelu(d0[mt][nt][1] + by));
                __half2 h1 = __floats2half2_rn(lrelu(d0[mt][nt][2] + bx), lrelu(d0[mt][nt][3] + by));
                *(__half2*)(smem + SM_Y0 + tile_off(row,     o, 256)) = h0;
                *(__half2*)(smem + SM_Y0 + tile_off(row + 8, o, 256)) = h1;
            }
    }

    // ---------------- layer1: D1[96,64], K=384; 16 warps: 48 rows x 8 outs ----------------
    float d1[3][4];
    #pragma unroll
    for (int i = 0; i < 3; i++)
        #pragma unroll
        for (int q = 0; q < 4; q++) d1[i][q] = 0.f;
    {
        const int m0 = (warp & 1) * 48;
        const int n0 = (warp >> 1) * 8;
        const int b1r = lane & 7, b1k = ((lane >> 3) & 1) * 8;
        for (int c = 0; c < 3; c++) {
            if (c < 2) {
                stage16k(sbase + SM_BUF + ((c + 1) & 1) * 16384, g_W1s + (c + 1) * 16384, tid);
                asm volatile("cp.async.wait_group 1;");
            } else {
                asm volatile("cp.async.wait_group 0;");
            }
            __syncthreads();          // chunk c + (c==0: y0) visible
            const unsigned bufc = sbase + SM_BUF + (c & 1) * 16384;
            const unsigned abase = (c == 0) ? (sbase + SM_Y0) : (sbase + SM_FEAT);
            const int S    = (c == 0) ? 256 : 512;
            const int kofs = (c == 2) ? 128 : 0;
            #pragma unroll
            for (int k16 = 0; k16 < 8; k16++) {
                const int kl = k16 * 16;
                unsigned a[3][4];
                #pragma unroll
                for (int mt = 0; mt < 3; mt++)
                    ldm_x4(a[mt], abase + tile_off(m0 + mt * 16 + ar, kofs + kl + ak, S));
                unsigned bfr[2];
                ldm_x2(bfr, bufc + tile_off(n0 + b1r, kl + b1k, 256));
                #pragma unroll
                for (int mt = 0; mt < 3; mt++)
                    mma_16816(d1[mt], a[mt], bfr[0], bfr[1]);
            }
            __syncthreads();
        }
    }

    // epilogue1 -> y1 (stride 128, aliases y0; safe: all L1 reads of y0 complete)
    {
        const int m0 = (warp & 1) * 48;
        const int n0 = (warp >> 1) * 8;
        #pragma unroll
        for (int mt = 0; mt < 3; mt++) {
            int row = m0 + mt * 16 + qr;
            int o   = n0 + qc;
            float bx = __ldg(b1 + o), by = __ldg(b1 + o + 1);
            __half2 h0 = __floats2half2_rn(lrelu(d1[mt][0] + bx), lrelu(d1[mt][1] + by));
            __half2 h1 = __floats2half2_rn(lrelu(d1[mt][2] + bx), lrelu(d1[mt][3] + by));
            *(__half2*)(smem + SM_Y1 + tile_off(row,     o, 128)) = h0;
            *(__half2*)(smem + SM_Y1 + tile_off(row + 8, o, 128)) = h1;
        }
    }
    __syncthreads();

    // ---------------- layer2: D2[96,8], K=320; warps 0..5 one m-tile each ----------------
    if (warp < 6) {
        float d2[4] = {0.f, 0.f, 0.f, 0.f};
        const int m0 = warp * 16;
        const int b2r = lane & 7, b2k = ((lane >> 3) & 1) * 8;
        #pragma unroll 4
        for (int k16 = 0; k16 < 20; k16++) {
            const int kk = k16 * 16;
            const unsigned abase = (kk < 64) ? (sbase + SM_Y1) : (sbase + SM_FEAT);
            const int S    = (kk < 64) ? 128 : 512;
            const int kloc = (kk < 64) ? kk : (kk - 64);
            unsigned a[4];
            ldm_x4(a, abase + tile_off(m0 + ar, kloc + ak, S));
            unsigned bfr[2];
            ldm_x2(bfr, sbase + SM_W2 + tile_off(b2r, kk + b2k, 640));
            mma_16816(d2, a, bfr[0], bfr[1]);
        }

        // epilogue2: relu + write out (5 valid cols)
        #pragma unroll
        for (int half = 0; half < 2; half++) {
            int pt = m0 + half * 8 + qr;
            int gp = tile * TILE_P + pt;
            if (gp < NPTS) {
                int b = gp / NN;
                int n = gp - b * NN;
                float v0 = d2[half * 2 + 0] + __ldg(b2 + qc);
                if (qc < 5)     out[b * (5 * NN) + qc * NN + n] = fmaxf(v0, 0.f);
                if (qc + 1 < 5) {
                    float v1 = d2[half * 2 + 1] + __ldg(b2 + qc + 1);
                    out[b * (5 * NN) + (qc + 1) * NN + n] = fmaxf(v1, 0.f);
                }
            }
        }
    }
}

extern "C" void kernel_launch(void* const* d_in, const int* in_sizes, int n_in,
                              void* d_out, int out_size) {
    const float* p   = (const float*)d_in[0];
    const float* cam = (const float*)d_in[1];
    const float* sf  = (const float*)d_in[2];
    const float* W0  = (const float*)d_in[3];
    const float* b0  = (const float*)d_in[4];
    const float* W1  = (const float*)d_in[5];
    const float* b1  = (const float*)d_in[6];
    const float* W2  = (const float*)d_in[7];
    const float* b2  = (const float*)d_in[8];
    float* out = (float*)d_out;

    dim3 tgrid(HW / 32, CC / 32, BB);
    transpose_kernel<<<tgrid, dim3(32, 8)>>>(sf, W0, W1, W2);

    cudaFuncSetAttribute(maf_fused, cudaFuncAttributeMaxDynamicSharedMemorySize, SM_TOTAL);
    maf_fused<<<NTILES, THREADS, SM_TOTAL>>>(p, cam, b0, b1, b2, out);
}

// round 14
// speedup vs baseline: 1.3089x; 1.3089x over previous
#include <cuda_runtime.h>
#include <cuda_fp16.h>
#include <math.h>

// ---------------- problem constants ----------------
#define BB 64
#define NN 431
#define CC 256
#define HH 56
#define WW 56
#define HW (HH*WW)            // 3136
#define NPTS (BB*NN)          // 27584
#define TILE_P 96
#define NTILES ((NPTS + TILE_P - 1) / TILE_P)   // 288 -> one wave at 2 blocks/SM
#define THREADS 256

// ---------------- smem map (byte offsets) ----------------
#define SM_FEAT 0                        // feat [96 r][256 k] fp16, stride 512B, swz (48KB)
#define SM_Y0   49152                    // y0 [96][128] fp16, stride 256B (24KB); params scratch pre-L0
#define SM_Y1   SM_Y0                    // y1 [96][64] fp16, stride 128B, aliases y0
#define SM_BUF  73728                    // 2 x 16KB weight double-buffer
#define SM_W2   106496                   // W2 [8][320] fp16, stride 640B (5KB = 320 x 16B lines)
#define SM_TOTAL 111616                  // -> 2 blocks/SM (223KB/SM)

// params scratch inside Y0 region (y0 written only after L0; gather done by then)
#define PRM_W   SM_Y0                    // float [4][96]  (1536B)
#define PRM_OFF (SM_Y0 + 1536)           // int   [4][96]  (1536B)

// ---------------- global scratch ----------------
// W0: 4 chunks of [128 o][64 k] (stride 128B, swz), 16KB each
// W1: 3 chunks of [64 o][128 k] (stride 256B, swz), 16KB each
__device__ __align__(16) unsigned char g_W0s[4*16384];
__device__ __align__(16) unsigned char g_W1s[3*16384];
__device__ __align__(16) unsigned char g_W2s[8*320*2];     // rows 5..7 zero
__device__ __half g_sfT[(size_t)BB * HW * CC];             // (B, HW, C) fp16

// ---------------- helpers ----------------
__device__ __forceinline__ int tile_off(int r, int k, int S) {
    int c16 = k >> 3;
    return r * S + ((((c16 & ~7) | ((c16 ^ r) & 7))) << 4) + ((k & 7) << 1);
}
__device__ __forceinline__ unsigned smem_u32(const void* p) {
    unsigned a;
    asm("{ .reg .u64 t; cvta.to.shared.u64 t, %1; cvt.u32.u64 %0, t; }" : "=r"(a) : "l"(p));
    return a;
}
__device__ __forceinline__ void cp_async16(unsigned sdst, const void* gsrc) {
    asm volatile("cp.async.cg.shared.global [%0], [%1], 16;" :: "r"(sdst), "l"(gsrc));
}
__device__ __forceinline__ void stage16k(unsigned sdst, const unsigned char* gsrc, int tid) {
    #pragma unroll
    for (int i = 0; i < 4; i++)
        cp_async16(sdst + (tid + i * 256) * 16, gsrc + (tid + i * 256) * 16);
    asm volatile("cp.async.commit_group;");
}
__device__ __forceinline__ void ldm_x4(unsigned r[4], unsigned addr) {
    asm volatile("ldmatrix.sync.aligned.m8n8.x4.shared.b16 {%0,%1,%2,%3}, [%4];"
                 : "=r"(r[0]), "=r"(r[1]), "=r"(r[2]), "=r"(r[3]) : "r"(addr));
}
__device__ __forceinline__ void ldm_x2(unsigned r[2], unsigned addr) {
    asm volatile("ldmatrix.sync.aligned.m8n8.x2.shared.b16 {%0,%1}, [%2];"
                 : "=r"(r[0]), "=r"(r[1]) : "r"(addr));
}
__device__ __forceinline__ void mma_16816(float d[4], const unsigned a[4], unsigned b0, unsigned b1) {
    asm volatile("mma.sync.aligned.m16n8k16.row.col.f32.f16.f16.f32 "
        "{%0,%1,%2,%3}, {%4,%5,%6,%7}, {%8,%9}, {%0,%1,%2,%3};"
        : "+f"(d[0]), "+f"(d[1]), "+f"(d[2]), "+f"(d[3])
        : "r"(a[0]), "r"(a[1]), "r"(a[2]), "r"(a[3]), "r"(b0), "r"(b1));
}
__device__ __forceinline__ float lrelu(float v) { return (v > 0.f) ? v : 0.01f * v; }

// ---------------- transpose + weight prep (unchanged, passing) ----------------
__global__ __launch_bounds__(256)
void transpose_kernel(const float* __restrict__ sf,
                      const float* __restrict__ W0,
                      const float* __restrict__ W1,
                      const float* __restrict__ W2) {
    __shared__ float tile[32][33];
    const int b  = blockIdx.z;
    const int c0 = blockIdx.y * 32;
    const int p0 = blockIdx.x * 32;
    const int tx = threadIdx.x, ty = threadIdx.y;
    const int t  = ty * 32 + tx;

    {   // weight prep over first 234 flat blocks (59904 = 234*256)
        int fb = (blockIdx.z * 8 + blockIdx.y) * 98 + blockIdx.x;
        if (fb < 234) {
            int i = fb * 256 + t;
            if (i < 32768) {
                int o = i >> 8, k = i & 255;
                *(__half*)(g_W0s + (k >> 6) * 16384 + tile_off(o, k & 63, 128)) =
                    __float2half(W0[o * 256 + k]);
            } else if (i < 32768 + 24576) {
                int j = i - 32768, o = j / 384, k = j - o * 384;
                *(__half*)(g_W1s + (k >> 7) * 16384 + tile_off(o, k & 127, 256)) =
                    __float2half(W1[o * 384 + k]);
            } else {
                int j = i - 32768 - 24576, o = j / 320, k = j - o * 320;
                float v = (o < 5) ? W2[o * 320 + k] : 0.f;
                *(__half*)(g_W2s + tile_off(o, k, 640)) = __float2half(v);
            }
        }
    }

    const float* src = sf + (size_t)b * CC * HW;
    #pragma unroll
    for (int j = 0; j < 4; j++)
        tile[ty * 4 + j][tx] = src[(size_t)(c0 + ty * 4 + j) * HW + p0 + tx];
    __syncthreads();
    const int pr  = t >> 3;
    const int ch4 = t & 7;
    __half2 v0 = __floats2half2_rn(tile[4 * ch4 + 0][pr], tile[4 * ch4 + 1][pr]);
    __half2 v1 = __floats2half2_rn(tile[4 * ch4 + 2][pr], tile[4 * ch4 + 3][pr]);
    uint2 pkt = make_uint2(*(unsigned*)&v0, *(unsigned*)&v1);
    uint2* dst = (uint2*)(g_sfT + (size_t)b * HW * CC + (size_t)(p0 + pr) * CC + c0);
    dst[ch4] = pkt;
}

// ---------------- fused: gather + 3-layer MLP, 96-pt tiles, 256 thr, 2 blocks/SM ----------------
__global__ __launch_bounds__(THREADS, 2)
void maf_fused(const float* __restrict__ p, const float* __restrict__ cam,
               const float* __restrict__ b0, const float* __restrict__ b1,
               const float* __restrict__ b2, float* __restrict__ out)
{
    extern __shared__ char smem[];
    const unsigned sbase = smem_u32(smem);
    const int tid  = threadIdx.x;
    const int warp = tid >> 5;
    const int lane = tid & 31;
    const int tile = blockIdx.x;

    // group 0: W2 (320 x 16B lines) + W0 chunk0
    {
        if (tid < 64) {
            #pragma unroll
            for (int i = 0; i < 5; i++)
                cp_async16(sbase + SM_W2 + (tid + i * 64) * 16, g_W2s + (tid + i * 64) * 16);
        }
        #pragma unroll
        for (int i = 0; i < 4; i++)
            cp_async16(sbase + SM_BUF + (tid + i * 256) * 16, g_W0s + (tid + i * 256) * 16);
        asm volatile("cp.async.commit_group;");
    }

    // point params -> smem (scratch in y0 region; y0 written only after L0)
    float* pW   = (float*)(smem + (PRM_W   - 0));
    int*   pOff = (int*)  (smem + (PRM_OFF - 0));
    if (tid < TILE_P) {
        int gp = tile * TILE_P + tid;
        if (gp >= NPTS) gp = NPTS - 1;            // clamp (last tile only)
        const int b = gp / NN;
        float s  = cam[b * 3 + 0];
        float tx = cam[b * 3 + 1];
        float ty = cam[b * 3 + 2];
        float gx = (s * (p[gp * 3 + 0] + tx) + 1.f) * (0.5f * (WW - 1));
        float gy = (s * (p[gp * 3 + 1] + ty) + 1.f) * (0.5f * (HH - 1));
        float x0f = floorf(gx), y0f = floorf(gy);
        float wx1 = gx - x0f, wy1 = gy - y0f;
        float wx0 = 1.f - wx1, wy0 = 1.f - wy1;
        if (!(x0f       >= 0.f && x0f       <= (float)(WW - 1))) wx0 = 0.f;
        if (!(x0f + 1.f >= 0.f && x0f + 1.f <= (float)(WW - 1))) wx1 = 0.f;
        if (!(y0f       >= 0.f && y0f       <= (float)(HH - 1))) wy0 = 0.f;
        if (!(y0f + 1.f >= 0.f && y0f + 1.f <= (float)(HH - 1))) wy1 = 0.f;
        int ix0 = (int)fminf(fmaxf(x0f,       0.f), (float)(WW - 1));
        int ix1 = (int)fminf(fmaxf(x0f + 1.f, 0.f), (float)(WW - 1));
        int iy0 = (int)fminf(fmaxf(y0f,       0.f), (float)(HH - 1));
        int iy1 = (int)fminf(fmaxf(y0f + 1.f, 0.f), (float)(HH - 1));
        int base = b * HW;
        pOff[0 * 96 + tid] = (base + iy0 * WW + ix0) * CC;
        pOff[1 * 96 + tid] = (base + iy0 * WW + ix1) * CC;
        pOff[2 * 96 + tid] = (base + iy1 * WW + ix0) * CC;
        pOff[3 * 96 + tid] = (base + iy1 * WW + ix1) * CC;
        pW[0 * 96 + tid] = wx0 * wy0; pW[1 * 96 + tid] = wx1 * wy0;
        pW[2 * 96 + tid] = wx0 * wy1; pW[3 * 96 + tid] = wx1 * wy1;
    }
    __syncthreads();

    // gather v2: warp owns 12 points; per (point,corner) the warp reads one FULL
    // contiguous 512B row (32 lanes x 16B) -> 4 dense wavefronts instead of 32.
    {
        const int p0i = warp * 12;
        #pragma unroll 2
        for (int i = 0; i < 12; i++) {
            const int pt = p0i + i;
            const float w00 = pW[0 * 96 + pt], w10 = pW[1 * 96 + pt];
            const float w01 = pW[2 * 96 + pt], w11 = pW[3 * 96 + pt];
            const __half* r00 = g_sfT + pOff[0 * 96 + pt] + lane * 8;
            const __half* r10 = g_sfT + pOff[1 * 96 + pt] + lane * 8;
            const __half* r01 = g_sfT + pOff[2 * 96 + pt] + lane * 8;
            const __half* r11 = g_sfT + pOff[3 * 96 + pt] + lane * 8;
            uint4 A  = *(const uint4*)r00;
            uint4 Bv = *(const uint4*)r10;
            uint4 Cv = *(const uint4*)r01;
            uint4 Dv = *(const uint4*)r11;
            __half2 hh[4];
            #pragma unroll
            for (int q = 0; q < 4; q++) {
                float2 fa = __half22float2(((const __half2*)&A)[q]);
                float2 fb = __half22float2(((const __half2*)&Bv)[q]);
                float2 fc = __half22float2(((const __half2*)&Cv)[q]);
                float2 fd = __half22float2(((const __half2*)&Dv)[q]);
                float rx = w00 * fa.x + w10 * fb.x + w01 * fc.x + w11 * fd.x;
                float ry = w00 * fa.y + w10 * fb.y + w01 * fc.y + w11 * fd.y;
                hh[q] = __floats2half2_rn(rx, ry);
            }
            // lane stores channels [lane*8, lane*8+8): c16 = lane -> conflict-free swz
            *(uint4*)(smem + SM_FEAT + tile_off(pt, lane * 8, 512)) = *(uint4*)hh;
        }
    }

    const int qr = lane >> 2;          // 0..7
    const int qc = (lane & 3) * 2;     // 0,2,4,6
    const int ar = lane & 15, ak = (lane >> 4) * 8;
    const int br = (lane & 7) + ((lane >> 4) << 3), bk = ((lane >> 3) & 1) * 8;

    // ---------------- layer0: D0[96,128], K=256; 8 warps: 48 rows x 32 outs ----------------
    float d0[3][4][4];
    #pragma unroll
    for (int i = 0; i < 3; i++)
        #pragma unroll
        for (int j = 0; j < 4; j++)
            #pragma unroll
            for (int q = 0; q < 4; q++) d0[i][j][q] = 0.f;
    {
        const int m0 = (warp & 1) * 48;
        const int n0 = (warp >> 1) * 32;
        for (int c = 0; c < 4; c++) {
            if (c < 3)
                stage16k(sbase + SM_BUF + ((c + 1) & 1) * 16384, g_W0s + (c + 1) * 16384, tid);
            else
                stage16k(sbase + SM_BUF + 0 * 16384, g_W1s, tid);
            asm volatile("cp.async.wait_group 1;");
            __syncthreads();          // chunk c (and gather/params on c==0) visible
            const unsigned bufc = sbase + SM_BUF + (c & 1) * 16384;
            #pragma unroll
            for (int k16 = 0; k16 < 4; k16++) {
                const int kg = c * 64 + k16 * 16;
                const int kl = k16 * 16;
                unsigned a[3][4];
                #pragma unroll
                for (int mt = 0; mt < 3; mt++)
                    ldm_x4(a[mt], sbase + SM_FEAT + tile_off(m0 + mt * 16 + ar, kg + ak, 512));
                #pragma unroll
                for (int nb = 0; nb < 2; nb++) {
                    unsigned bfr[4];
                    ldm_x4(bfr, bufc + tile_off(n0 + nb * 16 + br, kl + bk, 128));
                    #pragma unroll
                    for (int mt = 0; mt < 3; mt++) {
                        mma_16816(d0[mt][nb * 2 + 0], a[mt], bfr[0], bfr[1]);
                        mma_16816(d0[mt][nb * 2 + 1], a[mt], bfr[2], bfr[3]);
                    }
                }
            }
            __syncthreads();          // done with buf[c&1] before re-stage
        }
    }

    // epilogue0: bias + leaky -> y0 (stride 256); overlaps W1 chunk0 cp.async
    {
        const int m0 = (warp & 1) * 48;
        const int n0 = (warp >> 1) * 32;
        #pragma unroll
        for (int mt = 0; mt < 3; mt++)
            #pragma unroll
            for (int nt = 0; nt < 4; nt++) {
                int row = m0 + mt * 16 + qr;
                int o   = n0 + nt * 8 + qc;
                float bx = __ldg(b0 + o), by = __ldg(b0 + o + 1);
                __half2 h0 = __floats2half2_rn(lrelu(d0[mt][nt][0] + bx), lrelu(d0[mt][nt][1] + by));
                __half2 h1 = __floats2half2_rn(lrelu(d0[mt][nt][2] + bx), lrelu(d0[mt][nt][3] + by));
                *(__half2*)(smem + SM_Y0 + tile_off(row,     o, 256)) = h0;
                *(__half2*)(smem + SM_Y0 + tile_off(row + 8, o, 256)) = h1;
            }
    }

    // ---------------- layer1: D1[96,64], K=384; 8 warps: 48 rows x 16 outs ----------------
    float d1[3][2][4];
    #pragma unroll
    for (int i = 0; i < 3; i++)
        #pragma unroll
        for (int j = 0; j < 2; j++)
            #pragma unroll
            for (int q = 0; q < 4; q++) d1[i][j][q] = 0.f;
    {
        const int m0 = (warp & 1) * 48;
        const int n0 = (warp >> 1) * 16;
        for (int c = 0; c < 3; c++) {
            if (c < 2) {
                stage16k(sbase + SM_BUF + ((c + 1) & 1) * 16384, g_W1s + (c + 1) * 16384, tid);
                asm volatile("cp.async.wait_group 1;");
            } else {
                asm volatile("cp.async.wait_group 0;");
            }
            __syncthreads();          // chunk c + (c==0: y0) visible
            const unsigned bufc = sbase + SM_BUF + (c & 1) * 16384;
            const unsigned abase = (c == 0) ? (sbase + SM_Y0) : (sbase + SM_FEAT);
            const int S    = (c == 0) ? 256 : 512;
            const int kofs = (c == 2) ? 128 : 0;
            #pragma unroll
            for (int k16 = 0; k16 < 8; k16++) {
                const int kl = k16 * 16;
                unsigned a[3][4];
                #pragma unroll
                for (int mt = 0; mt < 3; mt++)
                    ldm_x4(a[mt], abase + tile_off(m0 + mt * 16 + ar, kofs + kl + ak, S));
                unsigned bfr[4];
                ldm_x4(bfr, bufc + tile_off(n0 + br, kl + bk, 256));
                #pragma unroll
                for (int mt = 0; mt < 3; mt++) {
                    mma_16816(d1[mt][0], a[mt], bfr[0], bfr[1]);
                    mma_16816(d1[mt][1], a[mt], bfr[2], bfr[3]);
                }
            }
            __syncthreads();
        }
    }

    // epilogue1 -> y1 (stride 128, aliases y0; safe: all L1 reads of y0 complete)
    {
        const int m0 = (warp & 1) * 48;
        const int n0 = (warp >> 1) * 16;
        #pragma unroll
        for (int mt = 0; mt < 3; mt++)
            #pragma unroll
            for (int nt = 0; nt < 2; nt++) {
                int row = m0 + mt * 16 + qr;
                int o   = n0 + nt * 8 + qc;
                float bx = __ldg(b1 + o), by = __ldg(b1 + o + 1);
                __half2 h0 = __floats2half2_rn(lrelu(d1[mt][nt][0] + bx), lrelu(d1[mt][nt][1] + by));
                __half2 h1 = __floats2half2_rn(lrelu(d1[mt][nt][2] + bx), lrelu(d1[mt][nt][3] + by));
                *(__half2*)(smem + SM_Y1 + tile_off(row,     o, 128)) = h0;
                *(__half2*)(smem + SM_Y1 + tile_off(row + 8, o, 128)) = h1;
            }
    }
    __syncthreads();

    // ---------------- layer2: D2[96,8], K=320; warps 0..5 one m-tile each ----------------
    if (warp < 6) {
        float d2[4] = {0.f, 0.f, 0.f, 0.f};
        const int m0 = warp * 16;
        const int b2r = lane & 7, b2k = ((lane >> 3) & 1) * 8;
        #pragma unroll 4
        for (int k16 = 0; k16 < 20; k16++) {
            const int kk = k16 * 16;
            const unsigned abase = (kk < 64) ? (sbase + SM_Y1) : (sbase + SM_FEAT);
            const int S    = (kk < 64) ? 128 : 512;
            const int kloc = (kk < 64) ? kk : (kk - 64);
            unsigned a[4];
            ldm_x4(a, abase + tile_off(m0 + ar, kloc + ak, S));
            unsigned bfr[2];
            ldm_x2(bfr, sbase + SM_W2 + tile_off(b2r, kk + b2k, 640));
            mma_16816(d2, a, bfr[0], bfr[1]);
        }

        // epilogue2: relu + write out (5 valid cols)
        #pragma unroll
        for (int half = 0; half < 2; half++) {
            int pt = m0 + half * 8 + qr;
            int gp = tile * TILE_P + pt;
            if (gp < NPTS) {
                int b = gp / NN;
                int n = gp - b * NN;
                float v0 = d2[half * 2 + 0] + __ldg(b2 + qc);
                if (qc < 5)     out[b * (5 * NN) + qc * NN + n] = fmaxf(v0, 0.f);
                if (qc + 1 < 5) {
                    float v1 = d2[half * 2 + 1] + __ldg(b2 + qc + 1);
                    out[b * (5 * NN) + (qc + 1) * NN + n] = fmaxf(v1, 0.f);
                }
            }
        }
    }
}

extern "C" void kernel_launch(void* const* d_in, const int* in_sizes, int n_in,
                              void* d_out, int out_size) {
    const float* p   = (const float*)d_in[0];
    const float* cam = (const float*)d_in[1];
    const float* sf  = (const float*)d_in[2];
    const float* W0  = (const float*)d_in[3];
    const float* b0  = (const float*)d_in[4];
    const float* W1  = (const float*)d_in[5];
    const float* b1  = (const float*)d_in[6];
    const float* W2  = (const float*)d_in[7];
    const float* b2  = (const float*)d_in[8];
    float* out = (float*)d_out;

    dim3 tgrid(HW / 32, CC / 32, BB);
    transpose_kernel<<<tgrid, dim3(32, 8)>>>(sf, W0, W1, W2);

    cudaFuncSetAttribute(maf_fused, cudaFuncAttributeMaxDynamicSharedMemorySize, SM_TOTAL);
    maf_fused<<<NTILES, THREADS, SM_TOTAL>>>(p, cam, b0, b1, b2, out);
}

// round 15
// speedup vs baseline: 1.5000x; 1.1460x over previous
#include <cuda_runtime.h>
#include <cuda_fp16.h>
#include <math.h>

// ---------------- problem constants ----------------
#define BB 64
#define NN 431
#define CC 256
#define HH 56
#define WW 56
#define HW (HH*WW)            // 3136
#define NPTS (BB*NN)          // 27584
#define TILE_P 96
#define NTILES ((NPTS + TILE_P - 1) / TILE_P)   // 288 -> one wave at 2 blocks/SM
#define THREADS 256

// ---------------- smem map (byte offsets) ----------------
#define SM_FEAT 0                        // feat [96 r][256 k] fp16, stride 512B, swz (48KB)
#define SM_Y0   49152                    // y0 [96][128] fp16, stride 256B (24KB); params scratch pre-L0
#define SM_Y1   SM_Y0                    // y1 [96][64] fp16, stride 128B, aliases y0
#define SM_BUF  73728                    // 2 x 16KB weight double-buffer
#define SM_W2   106496                   // W2 [8][320] fp16, stride 640B (5KB = 320 x 16B lines)
#define SM_TOTAL 111616                  // -> 2 blocks/SM (223KB/SM)

// params scratch inside Y0 region (y0 written only after L0; gather done by then)
#define PRM_W   SM_Y0                    // float [4][96]  (1536B)
#define PRM_OFF (SM_Y0 + 1536)           // int   [4][96]  (1536B)

// ---------------- global scratch ----------------
// W0: 4 chunks of [128 o][64 k] (stride 128B, swz), 16KB each
// W1: 3 chunks of [64 o][128 k] (stride 256B, swz), 16KB each
__device__ __align__(16) unsigned char g_W0s[4*16384];
__device__ __align__(16) unsigned char g_W1s[3*16384];
__device__ __align__(16) unsigned char g_W2s[8*320*2];     // rows 5..7 zero
__device__ __half g_sfT[(size_t)BB * HW * CC];             // (B, HW, C) fp16

// ---------------- helpers ----------------
__device__ __forceinline__ int tile_off(int r, int k, int S) {
    int c16 = k >> 3;
    return r * S + ((((c16 & ~7) | ((c16 ^ r) & 7))) << 4) + ((k & 7) << 1);
}
__device__ __forceinline__ unsigned smem_u32(const void* p) {
    unsigned a;
    asm("{ .reg .u64 t; cvta.to.shared.u64 t, %1; cvt.u32.u64 %0, t; }" : "=r"(a) : "l"(p));
    return a;
}
__device__ __forceinline__ void cp_async16(unsigned sdst, const void* gsrc) {
    asm volatile("cp.async.cg.shared.global [%0], [%1], 16;" :: "r"(sdst), "l"(gsrc));
}
__device__ __forceinline__ void stage16k(unsigned sdst, const unsigned char* gsrc, int tid) {
    #pragma unroll
    for (int i = 0; i < 4; i++)
        cp_async16(sdst + (tid + i * 256) * 16, gsrc + (tid + i * 256) * 16);
    asm volatile("cp.async.commit_group;");
}
__device__ __forceinline__ void ldm_x4(unsigned r[4], unsigned addr) {
    asm volatile("ldmatrix.sync.aligned.m8n8.x4.shared.b16 {%0,%1,%2,%3}, [%4];"
                 : "=r"(r[0]), "=r"(r[1]), "=r"(r[2]), "=r"(r[3]) : "r"(addr));
}
__device__ __forceinline__ void ldm_x2(unsigned r[2], unsigned addr) {
    asm volatile("ldmatrix.sync.aligned.m8n8.x2.shared.b16 {%0,%1}, [%2];"
                 : "=r"(r[0]), "=r"(r[1]) : "r"(addr));
}
__device__ __forceinline__ void mma_16816(float d[4], const unsigned a[4], unsigned b0, unsigned b1) {
    asm volatile("mma.sync.aligned.m16n8k16.row.col.f32.f16.f16.f32 "
        "{%0,%1,%2,%3}, {%4,%5,%6,%7}, {%8,%9}, {%0,%1,%2,%3};"
        : "+f"(d[0]), "+f"(d[1]), "+f"(d[2]), "+f"(d[3])
        : "r"(a[0]), "r"(a[1]), "r"(a[2]), "r"(a[3]), "r"(b0), "r"(b1));
}
__device__ __forceinline__ float lrelu(float v) { return (v > 0.f) ? v : 0.01f * v; }

// ---------------- transpose v2 + weight prep ----------------
// (B,C,H,W) f32 -> (B,HW,C) f16. Tile = 32 channels x 64 pixels (3136 = 49*64).
// float4 loads (2 per thread), conflict-free smem, one uint4 store per thread.
__global__ __launch_bounds__(256)
void transpose_kernel(const float* __restrict__ sf,
                      const float* __restrict__ W0,
                      const float* __restrict__ W1,
                      const float* __restrict__ W2) {
    __shared__ float tile[32][65];
    const int b  = blockIdx.z;
    const int c0 = blockIdx.y * 32;
    const int p0 = blockIdx.x * 64;
    const int tid = threadIdx.x;

    {   // weight prep over first 234 flat blocks (59904 = 234*256)
        int fb = (blockIdx.z * 8 + blockIdx.y) * 49 + blockIdx.x;
        if (fb < 234) {
            int i = fb * 256 + tid;
            if (i < 32768) {
                int o = i >> 8, k = i & 255;
                *(__half*)(g_W0s + (k >> 6) * 16384 + tile_off(o, k & 63, 128)) =
                    __float2half(W0[o * 256 + k]);
            } else if (i < 32768 + 24576) {
                int j = i - 32768, o = j / 384, k = j - o * 384;
                *(__half*)(g_W1s + (k >> 7) * 16384 + tile_off(o, k & 127, 256)) =
                    __float2half(W1[o * 384 + k]);
            } else {
                int j = i - 32768 - 24576, o = j / 320, k = j - o * 320;
                float v = (o < 5) ? W2[o * 320 + k] : 0.f;
                *(__half*)(g_W2s + tile_off(o, k, 640)) = __float2half(v);
            }
        }
    }

    // load: 512 float4 (32 ch x 16 f4) over 256 threads, 2 each
    const float* src = sf + (size_t)b * CC * HW;
    #pragma unroll
    for (int it = 0; it < 2; it++) {
        int e  = tid + it * 256;          // 0..511
        int ch = e >> 4;                  // 0..31
        int f4 = e & 15;                  // 0..15
        float4 v = *(const float4*)(src + (size_t)(c0 + ch) * HW + p0 + f4 * 4);
        tile[ch][f4 * 4 + 0] = v.x;
        tile[ch][f4 * 4 + 1] = v.y;
        tile[ch][f4 * 4 + 2] = v.z;
        tile[ch][f4 * 4 + 3] = v.w;
    }
    __syncthreads();

    // store: thread -> (pixel px = tid>>2, channel-8-group q = tid&3), one uint4
    const int px = tid >> 2;
    const int q  = tid & 3;
    __half2 h[4];
    #pragma unroll
    for (int s = 0; s < 4; s++)
        h[s] = __floats2half2_rn(tile[q * 8 + 2 * s][px], tile[q * 8 + 2 * s + 1][px]);
    uint4* dst = (uint4*)(g_sfT + (size_t)b * HW * CC + (size_t)(p0 + px) * CC + c0);
    dst[q] = *(uint4*)h;
}

// ---------------- fused: gather + 3-layer MLP, 96-pt tiles, 256 thr, 2 blocks/SM ----------------
__global__ __launch_bounds__(THREADS, 2)
void maf_fused(const float* __restrict__ p, const float* __restrict__ cam,
               const float* __restrict__ b0, const float* __restrict__ b1,
               const float* __restrict__ b2, float* __restrict__ out)
{
    extern __shared__ char smem[];
    const unsigned sbase = smem_u32(smem);
    const int tid  = threadIdx.x;
    const int warp = tid >> 5;
    const int lane = tid & 31;
    const int tile = blockIdx.x;

    // group 0: W2 (320 x 16B lines) + W0 chunk0
    {
        if (tid < 64) {
            #pragma unroll
            for (int i = 0; i < 5; i++)
                cp_async16(sbase + SM_W2 + (tid + i * 64) * 16, g_W2s + (tid + i * 64) * 16);
        }
        #pragma unroll
        for (int i = 0; i < 4; i++)
            cp_async16(sbase + SM_BUF + (tid + i * 256) * 16, g_W0s + (tid + i * 256) * 16);
        asm volatile("cp.async.commit_group;");
    }

    // point params -> smem (scratch in y0 region; y0 written only after L0)
    float* pW   = (float*)(smem + PRM_W);
    int*   pOff = (int*)  (smem + PRM_OFF);
    if (tid < TILE_P) {
        int gp = tile * TILE_P + tid;
        if (gp >= NPTS) gp = NPTS - 1;            // clamp (last tile only)
        const int b = gp / NN;
        float s  = cam[b * 3 + 0];
        float tx = cam[b * 3 + 1];
        float ty = cam[b * 3 + 2];
        float gx = (s * (p[gp * 3 + 0] + tx) + 1.f) * (0.5f * (WW - 1));
        float gy = (s * (p[gp * 3 + 1] + ty) + 1.f) * (0.5f * (HH - 1));
        float x0f = floorf(gx), y0f = floorf(gy);
        float wx1 = gx - x0f, wy1 = gy - y0f;
        float wx0 = 1.f - wx1, wy0 = 1.f - wy1;
        if (!(x0f       >= 0.f && x0f       <= (float)(WW - 1))) wx0 = 0.f;
        if (!(x0f + 1.f >= 0.f && x0f + 1.f <= (float)(WW - 1))) wx1 = 0.f;
        if (!(y0f       >= 0.f && y0f       <= (float)(HH - 1))) wy0 = 0.f;
        if (!(y0f + 1.f >= 0.f && y0f + 1.f <= (float)(HH - 1))) wy1 = 0.f;
        int ix0 = (int)fminf(fmaxf(x0f,       0.f), (float)(WW - 1));
        int ix1 = (int)fminf(fmaxf(x0f + 1.f, 0.f), (float)(WW - 1));
        int iy0 = (int)fminf(fmaxf(y0f,       0.f), (float)(HH - 1));
        int iy1 = (int)fminf(fmaxf(y0f + 1.f, 0.f), (float)(HH - 1));
        int base = b * HW;
        pOff[0 * 96 + tid] = (base + iy0 * WW + ix0) * CC;
        pOff[1 * 96 + tid] = (base + iy0 * WW + ix1) * CC;
        pOff[2 * 96 + tid] = (base + iy1 * WW + ix0) * CC;
        pOff[3 * 96 + tid] = (base + iy1 * WW + ix1) * CC;
        pW[0 * 96 + tid] = wx0 * wy0; pW[1 * 96 + tid] = wx1 * wy0;
        pW[2 * 96 + tid] = wx0 * wy1; pW[3 * 96 + tid] = wx1 * wy1;
    }
    __syncthreads();

    // gather: warp owns 12 points; per (point,corner) one full contiguous 512B row
    {
        const int p0i = warp * 12;
        #pragma unroll 2
        for (int i = 0; i < 12; i++) {
            const int pt = p0i + i;
            const float w00 = pW[0 * 96 + pt], w10 = pW[1 * 96 + pt];
            const float w01 = pW[2 * 96 + pt], w11 = pW[3 * 96 + pt];
            const __half* r00 = g_sfT + pOff[0 * 96 + pt] + lane * 8;
            const __half* r10 = g_sfT + pOff[1 * 96 + pt] + lane * 8;
            const __half* r01 = g_sfT + pOff[2 * 96 + pt] + lane * 8;
            const __half* r11 = g_sfT + pOff[3 * 96 + pt] + lane * 8;
            uint4 A  = *(const uint4*)r00;
            uint4 Bv = *(const uint4*)r10;
            uint4 Cv = *(const uint4*)r01;
            uint4 Dv = *(const uint4*)r11;
            __half2 hh[4];
            #pragma unroll
            for (int q = 0; q < 4; q++) {
                float2 fa = __half22float2(((const __half2*)&A)[q]);
                float2 fb = __half22float2(((const __half2*)&Bv)[q]);
                float2 fc = __half22float2(((const __half2*)&Cv)[q]);
                float2 fd = __half22float2(((const __half2*)&Dv)[q]);
                float rx = w00 * fa.x + w10 * fb.x + w01 * fc.x + w11 * fd.x;
                float ry = w00 * fa.y + w10 * fb.y + w01 * fc.y + w11 * fd.y;
                hh[q] = __floats2half2_rn(rx, ry);
            }
            *(uint4*)(smem + SM_FEAT + tile_off(pt, lane * 8, 512)) = *(uint4*)hh;
        }
    }

    const int qr = lane >> 2;          // 0..7
    const int qc = (lane & 3) * 2;     // 0,2,4,6
    const int ar = lane & 15, ak = (lane >> 4) * 8;
    const int br = (lane & 7) + ((lane >> 4) << 3), bk = ((lane >> 3) & 1) * 8;

    // ---------------- layer0: D0[96,128], K=256; 8 warps: 48 rows x 32 outs ----------------
    float d0[3][4][4];
    #pragma unroll
    for (int i = 0; i < 3; i++)
        #pragma unroll
        for (int j = 0; j < 4; j++)
            #pragma unroll
            for (int q = 0; q < 4; q++) d0[i][j][q] = 0.f;
    {
        const int m0 = (warp & 1) * 48;
        const int n0 = (warp >> 1) * 32;
        for (int c = 0; c < 4; c++) {
            if (c < 3)
                stage16k(sbase + SM_BUF + ((c + 1) & 1) * 16384, g_W0s + (c + 1) * 16384, tid);
            else
                stage16k(sbase + SM_BUF + 0 * 16384, g_W1s, tid);
            asm volatile("cp.async.wait_group 1;");
            __syncthreads();          // chunk c (and gather/params on c==0) visible
            const unsigned bufc = sbase + SM_BUF + (c & 1) * 16384;
            #pragma unroll
            for (int k16 = 0; k16 < 4; k16++) {
                const int kg = c * 64 + k16 * 16;
                const int kl = k16 * 16;
                unsigned a[3][4];
                #pragma unroll
                for (int mt = 0; mt < 3; mt++)
                    ldm_x4(a[mt], sbase + SM_FEAT + tile_off(m0 + mt * 16 + ar, kg + ak, 512));
                #pragma unroll
                for (int nb = 0; nb < 2; nb++) {
                    unsigned bfr[4];
                    ldm_x4(bfr, bufc + tile_off(n0 + nb * 16 + br, kl + bk, 128));
                    #pragma unroll
                    for (int mt = 0; mt < 3; mt++) {
                        mma_16816(d0[mt][nb * 2 + 0], a[mt], bfr[0], bfr[1]);
                        mma_16816(d0[mt][nb * 2 + 1], a[mt], bfr[2], bfr[3]);
                    }
                }
            }
            __syncthreads();          // done with buf[c&1] before re-stage
        }
    }

    // epilogue0: bias + leaky -> y0 (stride 256); overlaps W1 chunk0 cp.async
    {
        const int m0 = (warp & 1) * 48;
        const int n0 = (warp >> 1) * 32;
        #pragma unroll
        for (int mt = 0; mt < 3; mt++)
            #pragma unroll
            for (int nt = 0; nt < 4; nt++) {
                int row = m0 + mt * 16 + qr;
                int o   = n0 + nt * 8 + qc;
                float bx = __ldg(b0 + o), by = __ldg(b0 + o + 1);
                __half2 h0 = __floats2half2_rn(lrelu(d0[mt][nt][0] + bx), lrelu(d0[mt][nt][1] + by));
                __half2 h1 = __floats2half2_rn(lrelu(d0[mt][nt][2] + bx), lrelu(d0[mt][nt][3] + by));
                *(__half2*)(smem + SM_Y0 + tile_off(row,     o, 256)) = h0;
                *(__half2*)(smem + SM_Y0 + tile_off(row + 8, o, 256)) = h1;
            }
    }

    // ---------------- layer1: D1[96,64], K=384; 8 warps: 48 rows x 16 outs ----------------
    float d1[3][2][4];
    #pragma unroll
    for (int i = 0; i < 3; i++)
        #pragma unroll
        for (int j = 0; j < 2; j++)
            #pragma unroll
            for (int q = 0; q < 4; q++) d1[i][j][q] = 0.f;
    {
        const int m0 = (warp & 1) * 48;
        const int n0 = (warp >> 1) * 16;
        for (int c = 0; c < 3; c++) {
            if (c < 2) {
                stage16k(sbase + SM_BUF + ((c + 1) & 1) * 16384, g_W1s + (c + 1) * 16384, tid);
                asm volatile("cp.async.wait_group 1;");
            } else {
                asm volatile("cp.async.wait_group 0;");
            }
            __syncthreads();          // chunk c + (c==0: y0) visible
            const unsigned bufc = sbase + SM_BUF + (c & 1) * 16384;
            const unsigned abase = (c == 0) ? (sbase + SM_Y0) : (sbase + SM_FEAT);
            const int S    = (c == 0) ? 256 : 512;
            const int kofs = (c == 2) ? 128 : 0;
            #pragma unroll
            for (int k16 = 0; k16 < 8; k16++) {
                const int kl = k16 * 16;
                unsigned a[3][4];
                #pragma unroll
                for (int mt = 0; mt < 3; mt++)
                    ldm_x4(a[mt], abase + tile_off(m0 + mt * 16 + ar, kofs + kl + ak, S));
                unsigned bfr[4];
                ldm_x4(bfr, bufc + tile_off(n0 + br, kl + bk, 256));
                #pragma unroll
                for (int mt = 0; mt < 3; mt++) {
                    mma_16816(d1[mt][0], a[mt], bfr[0], bfr[1]);
                    mma_16816(d1[mt][1], a[mt], bfr[2], bfr[3]);
                }
            }
            __syncthreads();
        }
    }

    // epilogue1 -> y1 (stride 128, aliases y0; safe: all L1 reads of y0 complete)
    {
        const int m0 = (warp & 1) * 48;
        const int n0 = (warp >> 1) * 16;
        #pragma unroll
        for (int mt = 0; mt < 3; mt++)
            #pragma unroll
            for (int nt = 0; nt < 2; nt++) {
                int row = m0 + mt * 16 + qr;
                int o   = n0 + nt * 8 + qc;
                float bx = __ldg(b1 + o), by = __ldg(b1 + o + 1);
                __half2 h0 = __floats2half2_rn(lrelu(d1[mt][nt][0] + bx), lrelu(d1[mt][nt][1] + by));
                __half2 h1 = __floats2half2_rn(lrelu(d1[mt][nt][2] + bx), lrelu(d1[mt][nt][3] + by));
                *(__half2*)(smem + SM_Y1 + tile_off(row,     o, 128)) = h0;
                *(__half2*)(smem + SM_Y1 + tile_off(row + 8, o, 128)) = h1;
            }
    }
    __syncthreads();

    // ---------------- layer2: D2[96,8], K=320; warps 0..5 one m-tile each ----------------
    if (warp < 6) {
        float d2[4] = {0.f, 0.f, 0.f, 0.f};
        const int m0 = warp * 16;
        const int b2r = lane & 7, b2k = ((lane >> 3) & 1) * 8;
        #pragma unroll 4
        for (int k16 = 0; k16 < 20; k16++) {
            const int kk = k16 * 16;
            const unsigned abase = (kk < 64) ? (sbase + SM_Y1) : (sbase + SM_FEAT);
            const int S    = (kk < 64) ? 128 : 512;
            const int kloc = (kk < 64) ? kk : (kk - 64);
            unsigned a[4];
            ldm_x4(a, abase + tile_off(m0 + ar, kloc + ak, S));
            unsigned bfr[2];
            ldm_x2(bfr, sbase + SM_W2 + tile_off(b2r, kk + b2k, 640));
            mma_16816(d2, a, bfr[0], bfr[1]);
        }

        // epilogue2: relu + write out (5 valid cols)
        #pragma unroll
        for (int half = 0; half < 2; half++) {
            int pt = m0 + half * 8 + qr;
            int gp = tile * TILE_P + pt;
            if (gp < NPTS) {
                int b = gp / NN;
                int n = gp - b * NN;
                float v0 = d2[half * 2 + 0] + __ldg(b2 + qc);
                if (qc < 5)     out[b * (5 * NN) + qc * NN + n] = fmaxf(v0, 0.f);
                if (qc + 1 < 5) {
                    float v1 = d2[half * 2 + 1] + __ldg(b2 + qc + 1);
                    out[b * (5 * NN) + (qc + 1) * NN + n] = fmaxf(v1, 0.f);
                }
            }
        }
    }
}

extern "C" void kernel_launch(void* const* d_in, const int* in_sizes, int n_in,
                              void* d_out, int out_size) {
    const float* p   = (const float*)d_in[0];
    const float* cam = (const float*)d_in[1];
    const float* sf  = (const float*)d_in[2];
    const float* W0  = (const float*)d_in[3];
    const float* b0  = (const float*)d_in[4];
    const float* W1  = (const float*)d_in[5];
    const float* b1  = (const float*)d_in[6];
    const float* W2  = (const float*)d_in[7];
    const float* b2  = (const float*)d_in[8];
    float* out = (float*)d_out;

    dim3 tgrid(HW / 64, CC / 32, BB);   // (49, 8, 64)
    transpose_kernel<<<tgrid, 256>>>(sf, W0, W1, W2);

    cudaFuncSetAttribute(maf_fused, cudaFuncAttributeMaxDynamicSharedMemorySize, SM_TOTAL);
    maf_fused<<<NTILES, THREADS, SM_TOTAL>>>(p, cam, b0, b1, b2, out);
}